// round 3
// baseline (speedup 1.0000x reference)
#include <cuda_runtime.h>

#define NN   100000
#define NE   1600000
#define INF_ 128
#define OUTF 64

typedef unsigned long long u64;

__device__ float g_support[(size_t)NN * OUTF];
__device__ float g_resid[(size_t)NN * OUTF];

__device__ __forceinline__ u64 pack2(float a, float b) {
  u64 r; asm("mov.b64 %0, {%1, %2};" : "=l"(r) : "f"(a), "f"(b)); return r;
}
__device__ __forceinline__ void unpack2(u64 v, float& a, float& b) {
  asm("mov.b64 {%0, %1}, %2;" : "=f"(a), "=f"(b) : "l"(v));
}
__device__ __forceinline__ u64 ffma2(u64 a, u64 b, u64 c) {
  u64 d; asm("fma.rn.f32x2 %0, %1, %2, %3;" : "=l"(d) : "l"(a), "l"(b), "l"(c));
  return d;
}

// ---------------------------------------------------------------------------
// Kernel 1: fused dual GEMM with packed f32x2 FMAs.
//   g_support[n, f] = sum_k x[n,k] * weight[k,f]            (f in 0..63)
//   g_resid  [n, o] = sum_k x[n,k] * res_w[o,k] + res_b[o]  (o in 0..63)
// Combined weight tile Wc[128 k][128 f] in SMEM (f<64: weight, f>=64: res_w^T).
// 256 threads: tx = tid&15 -> 8 features (4 f32x2 pairs); ty = tid>>4 -> 4 nodes.
// Thread tile: 4 nodes x 8 features. TILE_M = 64 nodes/block.
// ---------------------------------------------------------------------------
#define TILE_M 64
#define KC     32
#define XSS    36
#define GEMM_SMEM ((128 * 128 + TILE_M * XSS) * 4)

__global__ void __launch_bounds__(256) gemm_kernel(
    const float* __restrict__ x, const float* __restrict__ weight,
    const float* __restrict__ res_w, const float* __restrict__ res_b) {
  extern __shared__ float smem[];
  float* Wc = smem;               // [128][128]
  float* xs = smem + 128 * 128;   // [TILE_M][XSS]
  const int tid = threadIdx.x;
  const int tx = tid & 15;        // feature octet: tx*8 .. tx*8+7 (of 128)
  const int ty = tid >> 4;        // node quad: ty*4 .. ty*4+3
  const int n0 = blockIdx.x * TILE_M;

  // Combined weight tile -> SMEM
  for (int i = tid; i < 128 * 64; i += 256) {
    int k = i >> 6, f = i & 63;
    Wc[k * 128 + f] = weight[i];              // weight [128,64] row-major
  }
  for (int i = tid; i < 64 * 128; i += 256) {
    int o = i >> 7, k = i & 127;
    Wc[k * 128 + 64 + o] = res_w[i];          // res_w [64,128] row-major
  }

  u64 acc[4][4];
#pragma unroll
  for (int i = 0; i < 4; i++)
#pragma unroll
    for (int j = 0; j < 4; j++) acc[i][j] = 0ull;

  const float* Wt = Wc + tx * 8;
  const float* xrow = xs + (ty * 4) * XSS;

  for (int k0 = 0; k0 < INF_; k0 += KC) {
    __syncthreads();
    // Stage x chunk: 64 nodes x 32 k, float4 coalesced
#pragma unroll
    for (int rep = 0; rep < 2; rep++) {
      int i = tid + rep * 256;
      int node = i >> 3;          // KC/4 == 8
      int kq = i & 7;
      int gn = n0 + node;
      float4 v = make_float4(0.f, 0.f, 0.f, 0.f);
      if (gn < NN) v = *(const float4*)(x + (size_t)gn * INF_ + k0 + kq * 4);
      *(float4*)(xs + node * XSS + kq * 4) = v;
    }
    __syncthreads();

    const float* Wk = Wt + k0 * 128;
#pragma unroll 8
    for (int kk = 0; kk < KC; kk++) {
      float4 wa = *(const float4*)(Wk + kk * 128);
      float4 wb = *(const float4*)(Wk + kk * 128 + 4);
      u64 w0 = pack2(wa.x, wa.y), w1 = pack2(wa.z, wa.w);
      u64 w2 = pack2(wb.x, wb.y), w3 = pack2(wb.z, wb.w);
#pragma unroll
      for (int i = 0; i < 4; i++) {
        float xv = xrow[i * XSS + kk];
        u64 xx = pack2(xv, xv);
        acc[i][0] = ffma2(w0, xx, acc[i][0]);
        acc[i][1] = ffma2(w1, xx, acc[i][1]);
        acc[i][2] = ffma2(w2, xx, acc[i][2]);
        acc[i][3] = ffma2(w3, xx, acc[i][3]);
      }
    }
  }

  // Epilogue: tx<8 -> support features; tx>=8 -> residual features (+res_b)
  if (tx < 8) {
    const int f = tx * 8;
#pragma unroll
    for (int i = 0; i < 4; i++) {
      int gn = n0 + ty * 4 + i;
      if (gn < NN) {
        float4 v0, v1;
        unpack2(acc[i][0], v0.x, v0.y); unpack2(acc[i][1], v0.z, v0.w);
        unpack2(acc[i][2], v1.x, v1.y); unpack2(acc[i][3], v1.z, v1.w);
        float* p = g_support + (size_t)gn * OUTF + f;
        *(float4*)p = v0;
        *(float4*)(p + 4) = v1;
      }
    }
  } else {
    const int f = (tx - 8) * 8;
    float4 rb0 = *(const float4*)(res_b + f);
    float4 rb1 = *(const float4*)(res_b + f + 4);
#pragma unroll
    for (int i = 0; i < 4; i++) {
      int gn = n0 + ty * 4 + i;
      if (gn < NN) {
        float4 v0, v1;
        unpack2(acc[i][0], v0.x, v0.y); unpack2(acc[i][1], v0.z, v0.w);
        unpack2(acc[i][2], v1.x, v1.y); unpack2(acc[i][3], v1.z, v1.w);
        v0.x += rb0.x; v0.y += rb0.y; v0.z += rb0.z; v0.w += rb0.w;
        v1.x += rb1.x; v1.y += rb1.y; v1.z += rb1.z; v1.w += rb1.w;
        float* p = g_resid + (size_t)gn * OUTF + f;
        *(float4*)p = v0;
        *(float4*)(p + 4) = v1;
      }
    }
  }
}

// ---------------------------------------------------------------------------
// Kernel 2: edge scatter. 16 threads/edge, one float4 each, red.global.add.v4.
// ---------------------------------------------------------------------------
__global__ void __launch_bounds__(256) scatter_kernel(
    const int* __restrict__ src, const int* __restrict__ dst,
    const float* __restrict__ ew, float* __restrict__ out) {
  unsigned t = blockIdx.x * 256u + threadIdx.x;
  unsigned e = t >> 4;
  unsigned q = t & 15;
  if (e >= NE) return;
  int s = __ldg(src + e);
  int d = __ldg(dst + e);
  float w = __ldg(ew + e);
  float4 v = __ldg((const float4*)(g_support + (size_t)s * OUTF) + q);
  v.x *= w; v.y *= w; v.z *= w; v.w *= w;
  float* p = out + (size_t)d * OUTF + q * 4;
  asm volatile("red.global.add.v4.f32 [%0], {%1, %2, %3, %4};"
               :: "l"(p), "f"(v.x), "f"(v.y), "f"(v.z), "f"(v.w)
               : "memory");
}

// ---------------------------------------------------------------------------
// Kernel 3: finalize. 16 lanes/node: +bias, LayerNorm(64), ReLU, +resid.
// ---------------------------------------------------------------------------
__global__ void __launch_bounds__(256) finalize_kernel(
    float* __restrict__ out, const float* __restrict__ bias,
    const float* __restrict__ gamma, const float* __restrict__ beta) {
  unsigned t = blockIdx.x * 256u + threadIdx.x;
  unsigned n = t >> 4;
  unsigned q = t & 15;
  if (n >= NN) return;

  float4 v = *(float4*)(out + (size_t)n * OUTF + q * 4);
  float4 b = *(const float4*)(bias + q * 4);
  v.x += b.x; v.y += b.y; v.z += b.z; v.w += b.w;

  float s  = v.x + v.y + v.z + v.w;
  float s2 = v.x * v.x + v.y * v.y + v.z * v.z + v.w * v.w;
#pragma unroll
  for (int m = 8; m >= 1; m >>= 1) {
    s  += __shfl_xor_sync(0xffffffffu, s, m);
    s2 += __shfl_xor_sync(0xffffffffu, s2, m);
  }
  float mu  = s * (1.f / 64.f);
  float var = s2 * (1.f / 64.f) - mu * mu;
  float inv = rsqrtf(var + 1e-5f);

  float4 g  = *(const float4*)(gamma + q * 4);
  float4 be = *(const float4*)(beta + q * 4);
  float4 r  = *(const float4*)(g_resid + (size_t)n * OUTF + q * 4);

  v.x = fmaxf((v.x - mu) * inv * g.x + be.x, 0.f) + r.x;
  v.y = fmaxf((v.y - mu) * inv * g.y + be.y, 0.f) + r.y;
  v.z = fmaxf((v.z - mu) * inv * g.z + be.z, 0.f) + r.z;
  v.w = fmaxf((v.w - mu) * inv * g.w + be.w, 0.f) + r.w;

  *(float4*)(out + (size_t)n * OUTF + q * 4) = v;
}

// ---------------------------------------------------------------------------
extern "C" void kernel_launch(void* const* d_in, const int* in_sizes, int n_in,
                              void* d_out, int out_size) {
  const float* x      = (const float*)d_in[0];
  const float* weight = (const float*)d_in[1];
  const float* bias   = (const float*)d_in[2];
  const float* gamma  = (const float*)d_in[3];
  const float* beta   = (const float*)d_in[4];
  const float* res_w  = (const float*)d_in[5];
  const float* res_b  = (const float*)d_in[6];
  const float* ew     = (const float*)d_in[7];
  const int*   esrc   = (const int*)d_in[8];
  const int*   edst   = (const int*)d_in[9];
  float* out = (float*)d_out;

  cudaFuncSetAttribute(gemm_kernel,
                       cudaFuncAttributeMaxDynamicSharedMemorySize, GEMM_SMEM);

  cudaMemsetAsync(d_out, 0, (size_t)NN * OUTF * sizeof(float), 0);

  gemm_kernel<<<(NN + TILE_M - 1) / TILE_M, 256, GEMM_SMEM>>>(x, weight, res_w, res_b);

  unsigned sblocks = (unsigned)(((long long)NE * 16 + 255) / 256);
  scatter_kernel<<<sblocks, 256>>>(esrc, edst, ew, out);

  unsigned fblocks = (unsigned)(((long long)NN * 16 + 255) / 256);
  finalize_kernel<<<fblocks, 256>>>(out, bias, gamma, beta);
}